// round 1
// baseline (speedup 1.0000x reference)
#include <cuda_runtime.h>
#include <cstdint>

// ComparatorNBit: A,B float32 [N,32] with values in {0,1}, MSB first.
// Soft-logic reference is exact Boolean algebra on {0,1}, so:
//   a_eq_b = (packed_a == packed_b), a_gt_b = (packed_a > packed_b)
// Output layout: d_out[0..N)   = a_gt_b
//                d_out[N..2N)  = a_eq_b
//
// 8 threads per row; each thread loads one float4 from A and one from B
// (warp = 4 consecutive rows = fully coalesced 512B segments), packs 4 bits,
// OR-butterfly across the 8-lane group, lane 0 compares + stores.

__global__ void __launch_bounds__(256) comparator_nbit_kernel(
    const float4* __restrict__ A4,
    const float4* __restrict__ B4,
    float* __restrict__ out,
    int n)
{
    int gid = blockIdx.x * blockDim.x + threadIdx.x;
    int row = gid >> 3;        // 8 threads per row
    int sub = gid & 7;         // which float4 within the row
    if (row >= n) return;

    float4 a = A4[(long long)row * 8 + sub];
    float4 b = B4[(long long)row * 8 + sub];

    // element e = sub*4 + j maps to bit (31 - e); MSB first.
    int base = 31 - sub * 4;
    unsigned pa = 0u, pb = 0u;
    pa |= (unsigned)(a.x > 0.5f) << base;
    pa |= (unsigned)(a.y > 0.5f) << (base - 1);
    pa |= (unsigned)(a.z > 0.5f) << (base - 2);
    pa |= (unsigned)(a.w > 0.5f) << (base - 3);
    pb |= (unsigned)(b.x > 0.5f) << base;
    pb |= (unsigned)(b.y > 0.5f) << (base - 1);
    pb |= (unsigned)(b.z > 0.5f) << (base - 2);
    pb |= (unsigned)(b.w > 0.5f) << (base - 3);

    // OR-butterfly within each 8-lane group (offsets 4,2,1 stay in-group).
    #pragma unroll
    for (int off = 4; off >= 1; off >>= 1) {
        pa |= __shfl_xor_sync(0xffffffffu, pa, off);
        pb |= __shfl_xor_sync(0xffffffffu, pb, off);
    }

    if (sub == 0) {
        out[row]     = (pa > pb)  ? 1.0f : 0.0f;  // a_gt_b
        out[n + row] = (pa == pb) ? 1.0f : 0.0f;  // a_eq_b
    }
}

extern "C" void kernel_launch(void* const* d_in, const int* in_sizes, int n_in,
                              void* d_out, int out_size)
{
    const float4* A4 = (const float4*)d_in[0];
    const float4* B4 = (const float4*)d_in[1];
    float* out = (float*)d_out;

    int n = in_sizes[0] / 32;              // rows
    long long total_threads = (long long)n * 8;
    int block = 256;
    int grid = (int)((total_threads + block - 1) / block);

    comparator_nbit_kernel<<<grid, block>>>(A4, B4, out, n);
}